// round 3
// baseline (speedup 1.0000x reference)
#include <cuda_runtime.h>
#include <cstdint>

#define N_NODES 100000
#define IN_CH 128
#define OUT_CH 128
#define N_REL 8

// Scratch: per-(relation,node) input-space aggregation + counts.
__device__ float g_H[(size_t)N_REL * N_NODES * IN_CH];   // 409.6 MB
__device__ float g_cnt[(size_t)N_REL * N_NODES];         // 3.2 MB

// ---------------------------------------------------------------------------
// Phase 2: edge scatter. One warp per edge: 32 lanes x float4 = 128 floats.
// Vectorized global reduction (red.global.add.v4.f32, sm_90+).
// NOTE: edge_index / edge_type arrive as int32 (JAX x64-disabled downcast).
// ---------------------------------------------------------------------------
__global__ void rgcn_scatter_kernel(const float* __restrict__ x,
                                    const int* __restrict__ ei,
                                    const int* __restrict__ et,
                                    int E, int N) {
    int gid = blockIdx.x * blockDim.x + threadIdx.x;
    int e = gid >> 5;
    int lane = gid & 31;
    if (e >= E) return;
    int src = ei[e];
    int dst = ei[E + e];
    int r = et[e];
    // In-range guard: never fault; a dtype surprise shows as rel_err instead.
    if ((unsigned)src >= (unsigned)N || (unsigned)dst >= (unsigned)N ||
        (unsigned)r >= (unsigned)N_REL) return;
    float4 v = ((const float4*)(x + (size_t)src * IN_CH))[lane];
    float* h = g_H + (((size_t)r * N + dst) * IN_CH) + lane * 4;
    asm volatile("red.global.add.v4.f32 [%0], {%1,%2,%3,%4};"
                 :: "l"(h), "f"(v.x), "f"(v.y), "f"(v.z), "f"(v.w)
                 : "memory");
    if (lane == 0)
        atomicAdd(g_cnt + (size_t)r * N + dst, 1.0f);
}

// ---------------------------------------------------------------------------
// Phase 3: out = sum_r (H_r / max(cnt_r,1)) @ W_r  +  x @ root  +  bias
// Block tile: 64 nodes x 128 cols; 256 threads; each thread 4m x 8n,
// held as 16 packed f32x2 accumulators fed by fma.rn.f32x2.
// ---------------------------------------------------------------------------
__device__ __forceinline__ unsigned long long splat2(float v) {
    unsigned long long r;
    asm("mov.b64 %0, {%1, %1};" : "=l"(r) : "r"(__float_as_uint(v)));
    return r;
}
__device__ __forceinline__ void fma2(unsigned long long& d,
                                     unsigned long long a,
                                     unsigned long long b) {
    asm("fma.rn.f32x2 %0, %1, %2, %0;" : "+l"(d) : "l"(a), "l"(b));
}

__global__ __launch_bounds__(256) void rgcn_gemm_kernel(
    const float* __restrict__ x,
    const float* __restrict__ weight,
    const float* __restrict__ root,
    const float* __restrict__ bias,
    float* __restrict__ out,
    int N)
{
    extern __shared__ float smem[];
    float* As = smem;                  // [64][128]
    float* Ws = smem + 64 * 128;       // [128][128]

    const int tid = threadIdx.x;
    const int nt = tid & 15;           // 16 col-groups x 8 cols
    const int mt = tid >> 4;           // 16 row-groups x 4 rows
    const int m0 = blockIdx.x * 64;

    unsigned long long acc[4][4];
    #pragma unroll
    for (int i = 0; i < 4; i++)
        #pragma unroll
        for (int j = 0; j < 4; j++) acc[i][j] = 0ULL;

    for (int mat = 0; mat < 9; mat++) {
        // ---- load W tile (128x128) ----
        const float4* Wsrc = (const float4*)((mat < 8)
                                ? (weight + (size_t)mat * IN_CH * OUT_CH)
                                : root);
        #pragma unroll
        for (int i = 0; i < 16; i++) {
            int idx = tid + i * 256;          // 4096 float4
            ((float4*)Ws)[idx] = Wsrc[idx];
        }
        // ---- load A tile (64x128), with per-row mean scaling for relations ----
        #pragma unroll
        for (int i = 0; i < 8; i++) {
            int idx = tid + i * 256;          // 2048 float4 over [64][32]
            int row = idx >> 5;
            int gr = m0 + row;
            float4 v = make_float4(0.f, 0.f, 0.f, 0.f);
            if (gr < N) {
                if (mat < 8) {
                    size_t base = (size_t)mat * N + gr;
                    v = ((const float4*)(g_H + base * IN_CH))[idx & 31];
                    float inv = 1.0f / fmaxf(g_cnt[base], 1.0f);
                    v.x *= inv; v.y *= inv; v.z *= inv; v.w *= inv;
                } else {
                    v = ((const float4*)(x + (size_t)gr * IN_CH))[idx & 31];
                }
            }
            ((float4*)As)[idx] = v;
        }
        __syncthreads();

        // ---- inner product, k unrolled by 4 ----
        for (int k = 0; k < 128; k += 4) {
            float4 a[4];
            #pragma unroll
            for (int i = 0; i < 4; i++)
                a[i] = ((const float4*)As)[(mt * 4 + i) * 32 + (k >> 2)];
            #pragma unroll
            for (int kk = 0; kk < 4; kk++) {
                const ulonglong2* wrow =
                    (const ulonglong2*)(Ws + (size_t)(k + kk) * 128) + nt * 2;
                ulonglong2 wA = wrow[0];
                ulonglong2 wB = wrow[1];
                #pragma unroll
                for (int i = 0; i < 4; i++) {
                    float av = (kk == 0) ? a[i].x :
                               (kk == 1) ? a[i].y :
                               (kk == 2) ? a[i].z : a[i].w;
                    unsigned long long s = splat2(av);
                    fma2(acc[i][0], s, wA.x);
                    fma2(acc[i][1], s, wA.y);
                    fma2(acc[i][2], s, wB.x);
                    fma2(acc[i][3], s, wB.y);
                }
            }
        }
        __syncthreads();
    }

    // ---- epilogue: + bias, store ----
    float bb[8];
    #pragma unroll
    for (int j = 0; j < 8; j++) bb[j] = bias[nt * 8 + j];
    #pragma unroll
    for (int i = 0; i < 4; i++) {
        int gr = m0 + mt * 4 + i;
        if (gr >= N) continue;
        float* orow = out + (size_t)gr * OUT_CH + nt * 8;
        #pragma unroll
        for (int j = 0; j < 4; j++) {
            unsigned long long u = acc[i][j];
            float2 o;
            o.x = __uint_as_float((unsigned)u) + bb[j * 2];
            o.y = __uint_as_float((unsigned)(u >> 32)) + bb[j * 2 + 1];
            *(float2*)(orow + j * 2) = o;
        }
    }
}

// ---------------------------------------------------------------------------
extern "C" void kernel_launch(void* const* d_in, const int* in_sizes, int n_in,
                              void* d_out, int out_size) {
    const float* x      = (const float*)d_in[0];
    const int* ei       = (const int*)d_in[1];   // int32 (JAX x64-off downcast)
    const int* et       = (const int*)d_in[2];   // int32
    const float* weight = (const float*)d_in[3];
    const float* root   = (const float*)d_in[4];
    const float* bias   = (const float*)d_in[5];
    float* out = (float*)d_out;

    int N = in_sizes[0] / IN_CH;
    int E = in_sizes[2];

    // Phase 1: zero the aggregation scratch (memset nodes in the graph).
    void* hp = nullptr; cudaGetSymbolAddress(&hp, g_H);
    void* cp = nullptr; cudaGetSymbolAddress(&cp, g_cnt);
    cudaMemsetAsync(hp, 0, (size_t)N_REL * N * IN_CH * sizeof(float), 0);
    cudaMemsetAsync(cp, 0, (size_t)N_REL * N * sizeof(float), 0);

    // Phase 2: edge scatter (warp per edge).
    {
        long long threads = (long long)E * 32;
        int blocks = (int)((threads + 255) / 256);
        rgcn_scatter_kernel<<<blocks, 256>>>(x, ei, et, E, N);
    }

    // Phase 3: fused 9-matrix GEMM + bias.
    cudaFuncSetAttribute(rgcn_gemm_kernel,
                         cudaFuncAttributeMaxDynamicSharedMemorySize, 96 * 1024);
    rgcn_gemm_kernel<<<(N + 63) / 64, 256, 96 * 1024>>>(x, weight, root, bias,
                                                        out, N);
}

// round 9
// speedup vs baseline: 1.2138x; 1.2138x over previous
#include <cuda_runtime.h>
#include <cuda_bf16.h>
#include <cstdint>

#define N_NODES 100000
#define IN_CH 128
#define OUT_CH 128
#define N_REL 8
#define NMATS 9

// Scratch: per-(relation,node) input-space aggregation + counts.
__device__ float g_H[(size_t)N_REL * N_NODES * IN_CH];   // 409.6 MB
__device__ float g_cnt[(size_t)N_REL * N_NODES];         // 3.2 MB
// Pre-split, pre-swizzled bf16 weight images (exact SMEM byte images).
__device__ __align__(16) unsigned char g_Whi[NMATS * 32768];
__device__ __align__(16) unsigned char g_Wlo[NMATS * 32768];

// ---------------------------------------------------------------------------
// ldmatrix-friendly swizzled layout for a [128 rows][128 bf16 cols] tile:
// 256B per row; 16B chunk index c (0..15) stored at (c ^ (row & 7)).
// ---------------------------------------------------------------------------
__device__ __forceinline__ uint32_t swz_off(int row, int chunk) {
    return (uint32_t)(row * 256 + ((chunk ^ (row & 7)) << 4));
}

// ---------------------------------------------------------------------------
// Phase 0: pre-split W (+root) into bf16 hi/lo, stored transposed (row=n,
// col=k) in the swizzled smem image layout.
// ---------------------------------------------------------------------------
__global__ void prep_w_kernel(const float* __restrict__ w,
                              const float* __restrict__ root) {
    int mat = blockIdx.x;
    const float* src = (mat < 8) ? (w + (size_t)mat * 16384) : root;
    unsigned char* dh = g_Whi + (size_t)mat * 32768;
    unsigned char* dl = g_Wlo + (size_t)mat * 32768;
    for (int idx = threadIdx.x; idx < 16384; idx += blockDim.x) {
        int k = idx >> 7, n = idx & 127;     // src is W[k][n]
        float v = src[idx];
        __nv_bfloat16 hi = __float2bfloat16(v);
        __nv_bfloat16 lo = __float2bfloat16(v - __bfloat162float(hi));
        uint32_t off = swz_off(n, k >> 3) + (uint32_t)((k & 7) * 2);
        *(__nv_bfloat16*)(dh + off) = hi;
        *(__nv_bfloat16*)(dl + off) = lo;
    }
}

// ---------------------------------------------------------------------------
// Phase 2: edge scatter. One warp per edge: 32 lanes x float4 = 128 floats.
// ---------------------------------------------------------------------------
__global__ void rgcn_scatter_kernel(const float* __restrict__ x,
                                    const int* __restrict__ ei,
                                    const int* __restrict__ et,
                                    int E, int N) {
    int gid = blockIdx.x * blockDim.x + threadIdx.x;
    int e = gid >> 5;
    int lane = gid & 31;
    if (e >= E) return;
    int src = ei[e];
    int dst = ei[E + e];
    int r = et[e];
    if ((unsigned)src >= (unsigned)N || (unsigned)dst >= (unsigned)N ||
        (unsigned)r >= (unsigned)N_REL) return;
    float4 v = ((const float4*)(x + (size_t)src * IN_CH))[lane];
    float* h = g_H + (((size_t)r * N + dst) * IN_CH) + lane * 4;
    asm volatile("red.global.add.v4.f32 [%0], {%1,%2,%3,%4};"
                 :: "l"(h), "f"(v.x), "f"(v.y), "f"(v.z), "f"(v.w)
                 : "memory");
    if (lane == 0)
        atomicAdd(g_cnt + (size_t)r * N + dst, 1.0f);
}

// ---------------------------------------------------------------------------
// mma.sync helpers (sm_80-class path; works on sm_103 non-'a')
// ---------------------------------------------------------------------------
__device__ __forceinline__ uint32_t smem_u32(const void* p) {
    uint32_t a;
    asm("{ .reg .u64 t; cvta.to.shared.u64 t, %1; cvt.u32.u64 %0, t; }"
        : "=r"(a) : "l"(p));
    return a;
}
__device__ __forceinline__ void ldsm4(uint32_t* r, uint32_t addr) {
    asm volatile("ldmatrix.sync.aligned.m8n8.x4.shared.b16 {%0,%1,%2,%3}, [%4];"
                 : "=r"(r[0]), "=r"(r[1]), "=r"(r[2]), "=r"(r[3]) : "r"(addr));
}
__device__ __forceinline__ void mma16816(float* d, const uint32_t* a,
                                         const uint32_t* b) {
    asm volatile(
        "mma.sync.aligned.m16n8k16.row.col.f32.bf16.bf16.f32 "
        "{%0,%1,%2,%3}, {%4,%5,%6,%7}, {%8,%9}, {%0,%1,%2,%3};"
        : "+f"(d[0]), "+f"(d[1]), "+f"(d[2]), "+f"(d[3])
        : "r"(a[0]), "r"(a[1]), "r"(a[2]), "r"(a[3]), "r"(b[0]), "r"(b[1]));
}

// ---------------------------------------------------------------------------
// Phase 3: fused GEMM via bf16 3-product split on mma.sync.
// CTA tile 128x128 over K=9*128; 8 warps (4m x 2n), warp tile 32m x 64n.
// ---------------------------------------------------------------------------
#define S_A_HI 0
#define S_A_LO 32768
#define S_B_HI 65536
#define S_B_LO 98304
#define S_BIAS 131072
#define SMEM_TOT (131072 + 512)

__global__ __launch_bounds__(256) void rgcn_gemm_mma(
    const float* __restrict__ x,
    const float* __restrict__ bias,
    float* __restrict__ out,
    int N)
{
    extern __shared__ unsigned char smem[];
    const int tid = threadIdx.x, wid = tid >> 5, lane = tid & 31;
    const int wm = wid & 3;          // 4 m-blocks of 32 rows
    const int wn = wid >> 2;         // 2 n-blocks of 64 cols
    const int m0 = blockIdx.x * 128;

    if (tid < 128) *(float*)(smem + S_BIAS + tid * 4) = bias[tid];

    float acc[2][8][4];
    #pragma unroll
    for (int i = 0; i < 2; i++)
        #pragma unroll
        for (int j = 0; j < 8; j++)
            #pragma unroll
            for (int t = 0; t < 4; t++) acc[i][j][t] = 0.f;

    // Precompute ldmatrix lane->row pieces.
    const int a_row = wm * 32 + (lane & 7) + ((lane >> 3) & 1) * 8;  // + mi*16
    const int a_cl  = lane >> 4;                                     // k-chunk sel
    const int b_row = wn * 64 + (lane & 7) + ((lane >> 4) << 3);     // + nj*16
    const int b_cl  = (lane >> 3) & 1;

    for (int mat = 0; mat < NMATS; mat++) {
        // ---- copy pre-swizzled W images (identity float4 copy) ----
        const float4* wh = (const float4*)(g_Whi + (size_t)mat * 32768);
        const float4* wl = (const float4*)(g_Wlo + (size_t)mat * 32768);
        #pragma unroll
        for (int i = 0; i < 8; i++) {
            int idx = tid + i * 256;
            ((float4*)(smem + S_B_HI))[idx] = wh[idx];
            ((float4*)(smem + S_B_LO))[idx] = wl[idx];
        }
        // ---- A tile: load fp32, mean-scale, split hi/lo, swizzled store ----
        #pragma unroll
        for (int i = 0; i < 16; i++) {
            int idx = tid + i * 256;           // 4096 float4 over [128][32]
            int row = idx >> 5, c4 = idx & 31;
            int gr = m0 + row;
            float4 v = make_float4(0.f, 0.f, 0.f, 0.f);
            if (gr < N) {
                if (mat < 8) {
                    size_t base = (size_t)mat * N + gr;
                    v = ((const float4*)(g_H + base * IN_CH))[c4];
                    float inv = 1.0f / fmaxf(g_cnt[base], 1.0f);
                    v.x *= inv; v.y *= inv; v.z *= inv; v.w *= inv;
                } else {
                    v = ((const float4*)(x + (size_t)gr * IN_CH))[c4];
                }
            }
            __nv_bfloat162 h0 = __floats2bfloat162_rn(v.x, v.y);
            __nv_bfloat162 h1 = __floats2bfloat162_rn(v.z, v.w);
            __nv_bfloat162 l0 = __floats2bfloat162_rn(v.x - __bfloat162float(h0.x),
                                                      v.y - __bfloat162float(h0.y));
            __nv_bfloat162 l1 = __floats2bfloat162_rn(v.z - __bfloat162float(h1.x),
                                                      v.w - __bfloat162float(h1.y));
            uint32_t off = swz_off(row, c4 >> 1) + (uint32_t)((c4 & 1) * 8);
            uint2 uh; uh.x = *(uint32_t*)&h0; uh.y = *(uint32_t*)&h1;
            uint2 ul; ul.x = *(uint32_t*)&l0; ul.y = *(uint32_t*)&l1;
            *(uint2*)(smem + S_A_HI + off) = uh;
            *(uint2*)(smem + S_A_LO + off) = ul;
        }
        __syncthreads();

        // ---- 3 passes x 8 k16-steps ----
        #pragma unroll
        for (int pass = 0; pass < 3; pass++) {
            uint32_t As = smem_u32(smem + ((pass == 1) ? S_A_LO : S_A_HI));
            uint32_t Bs = smem_u32(smem + ((pass == 2) ? S_B_LO : S_B_HI));
            #pragma unroll
            for (int ks = 0; ks < 8; ks++) {
                uint32_t a[2][4], b[4][4];
                #pragma unroll
                for (int mi = 0; mi < 2; mi++) {
                    int r = a_row + mi * 16;
                    ldsm4(a[mi], As + swz_off(r, ks * 2 + a_cl));
                }
                #pragma unroll
                for (int nj = 0; nj < 4; nj++) {
                    int r = b_row + nj * 16;
                    ldsm4(b[nj], Bs + swz_off(r, ks * 2 + b_cl));
                }
                #pragma unroll
                for (int mi = 0; mi < 2; mi++)
                    #pragma unroll
                    for (int n8 = 0; n8 < 8; n8++)
                        mma16816(acc[mi][n8], a[mi], b[n8 >> 1] + (n8 & 1) * 2);
            }
        }
        __syncthreads();
    }

    // ---- epilogue: d-frag rows (lane>>2, +8), cols (lane&3)*2 ----
    const float* sbias = (const float*)(smem + S_BIAS);
    #pragma unroll
    for (int mi = 0; mi < 2; mi++) {
        #pragma unroll
        for (int n8 = 0; n8 < 8; n8++) {
            int col = wn * 64 + n8 * 8 + (lane & 3) * 2;
            float b0 = sbias[col], b1 = sbias[col + 1];
            int r0 = m0 + wm * 32 + mi * 16 + (lane >> 2);
            if (r0 < N) {
                float2 o; o.x = acc[mi][n8][0] + b0; o.y = acc[mi][n8][1] + b1;
                *(float2*)(out + (size_t)r0 * OUT_CH + col) = o;
            }
            int r1 = r0 + 8;
            if (r1 < N) {
                float2 o; o.x = acc[mi][n8][2] + b0; o.y = acc[mi][n8][3] + b1;
                *(float2*)(out + (size_t)r1 * OUT_CH + col) = o;
            }
        }
    }
}

// ---------------------------------------------------------------------------
extern "C" void kernel_launch(void* const* d_in, const int* in_sizes, int n_in,
                              void* d_out, int out_size) {
    const float* x      = (const float*)d_in[0];
    const int* ei       = (const int*)d_in[1];   // int32 (JAX x64-off downcast)
    const int* et       = (const int*)d_in[2];   // int32
    const float* weight = (const float*)d_in[3];
    const float* root   = (const float*)d_in[4];
    const float* bias   = (const float*)d_in[5];
    float* out = (float*)d_out;

    int N = in_sizes[0] / IN_CH;
    int E = in_sizes[2];

    // Phase 0: pre-split/swizzle W.
    prep_w_kernel<<<NMATS, 256>>>(weight, root);

    // Phase 1: zero the aggregation scratch.
    void* hp = nullptr; cudaGetSymbolAddress(&hp, g_H);
    void* cp = nullptr; cudaGetSymbolAddress(&cp, g_cnt);
    cudaMemsetAsync(hp, 0, (size_t)N_REL * N * IN_CH * sizeof(float), 0);
    cudaMemsetAsync(cp, 0, (size_t)N_REL * N * sizeof(float), 0);

    // Phase 2: edge scatter (warp per edge).
    {
        long long threads = (long long)E * 32;
        int blocks = (int)((threads + 255) / 256);
        rgcn_scatter_kernel<<<blocks, 256>>>(x, ei, et, E, N);
    }

    // Phase 3: mma.sync GEMM.
    cudaFuncSetAttribute(rgcn_gemm_mma,
                         cudaFuncAttributeMaxDynamicSharedMemorySize, SMEM_TOT);
    rgcn_gemm_mma<<<(N + 127) / 128, 256, SMEM_TOT>>>(x, bias, out, N);
}

// round 10
// speedup vs baseline: 1.6708x; 1.3765x over previous
#include <cuda_runtime.h>
#include <cuda_bf16.h>
#include <cstdint>

#define N_NODES 100000
#define IN_CH 128
#define OUT_CH 128
#define N_REL 8
#define NMATS 9

// Scratch: per-(relation,node) input-space aggregation + counts.
__device__ float g_H[(size_t)N_REL * N_NODES * IN_CH];   // 409.6 MB
__device__ float g_cnt[(size_t)N_REL * N_NODES];         // 3.2 MB
// Pre-split, pre-swizzled bf16 weight images (exact SMEM byte images).
__device__ __align__(16) unsigned char g_Whi[NMATS * 32768];
__device__ __align__(16) unsigned char g_Wlo[NMATS * 32768];

// ---------------------------------------------------------------------------
// ldmatrix-friendly swizzled layout for a [128 rows][128 bf16 cols] tile:
// 256B per row; 16B chunk index c (0..15) stored at (c ^ (row & 7)).
// ---------------------------------------------------------------------------
__device__ __forceinline__ uint32_t swz_off(int row, int chunk) {
    return (uint32_t)(row * 256 + ((chunk ^ (row & 7)) << 4));
}

// ---------------------------------------------------------------------------
// Phase 0: pre-split W (+root) into bf16 hi/lo, stored transposed (row=n,
// col=k) in the swizzled smem image layout.  Grid (9 mats x 8 slices).
// ---------------------------------------------------------------------------
__global__ void prep_w_kernel(const float* __restrict__ w,
                              const float* __restrict__ root) {
    int mat = blockIdx.x;
    int sub = blockIdx.y;
    const float* src = (mat < 8) ? (w + (size_t)mat * 16384) : root;
    unsigned char* dh = g_Whi + (size_t)mat * 32768;
    unsigned char* dl = g_Wlo + (size_t)mat * 32768;
    int end = (sub + 1) * 2048;
    for (int idx = sub * 2048 + threadIdx.x; idx < end; idx += blockDim.x) {
        int k = idx >> 7, n = idx & 127;     // src is W[k][n]
        float v = src[idx];
        __nv_bfloat16 hi = __float2bfloat16(v);
        __nv_bfloat16 lo = __float2bfloat16(v - __bfloat162float(hi));
        uint32_t off = swz_off(n, k >> 3) + (uint32_t)((k & 7) * 2);
        *(__nv_bfloat16*)(dh + off) = hi;
        *(__nv_bfloat16*)(dl + off) = lo;
    }
}

// ---------------------------------------------------------------------------
// Phase 2: edge scatter. One warp per edge: 32 lanes x float4 = 128 floats.
// ---------------------------------------------------------------------------
__global__ void rgcn_scatter_kernel(const float* __restrict__ x,
                                    const int* __restrict__ ei,
                                    const int* __restrict__ et,
                                    int E, int N) {
    int gid = blockIdx.x * blockDim.x + threadIdx.x;
    int e = gid >> 5;
    int lane = gid & 31;
    if (e >= E) return;
    int src = ei[e];
    int dst = ei[E + e];
    int r = et[e];
    if ((unsigned)src >= (unsigned)N || (unsigned)dst >= (unsigned)N ||
        (unsigned)r >= (unsigned)N_REL) return;
    float4 v = ((const float4*)(x + (size_t)src * IN_CH))[lane];
    float* h = g_H + (((size_t)r * N + dst) * IN_CH) + lane * 4;
    asm volatile("red.global.add.v4.f32 [%0], {%1,%2,%3,%4};"
                 :: "l"(h), "f"(v.x), "f"(v.y), "f"(v.z), "f"(v.w)
                 : "memory");
    if (lane == 0)
        atomicAdd(g_cnt + (size_t)r * N + dst, 1.0f);
}

// ---------------------------------------------------------------------------
// mma.sync helpers (sm_80-class path; works on sm_103 non-'a')
// ---------------------------------------------------------------------------
__device__ __forceinline__ uint32_t smem_u32(const void* p) {
    uint32_t a;
    asm("{ .reg .u64 t; cvta.to.shared.u64 t, %1; cvt.u32.u64 %0, t; }"
        : "=r"(a) : "l"(p));
    return a;
}
__device__ __forceinline__ void ldsm4(uint32_t* r, uint32_t addr) {
    asm volatile("ldmatrix.sync.aligned.m8n8.x4.shared.b16 {%0,%1,%2,%3}, [%4];"
                 : "=r"(r[0]), "=r"(r[1]), "=r"(r[2]), "=r"(r[3]) : "r"(addr));
}
__device__ __forceinline__ void mma16816(float* d, const uint32_t* a,
                                         const uint32_t* b) {
    asm volatile(
        "mma.sync.aligned.m16n8k16.row.col.f32.bf16.bf16.f32 "
        "{%0,%1,%2,%3}, {%4,%5,%6,%7}, {%8,%9}, {%0,%1,%2,%3};"
        : "+f"(d[0]), "+f"(d[1]), "+f"(d[2]), "+f"(d[3])
        : "r"(a[0]), "r"(a[1]), "r"(a[2]), "r"(a[3]), "r"(b[0]), "r"(b[1]));
}

// ---------------------------------------------------------------------------
// Phase 3: fused GEMM via bf16 3-product split on mma.sync.
// CTA tile 128x128 over K=9*128; 8 warps (4m x 2n), warp tile 32m x 64n.
// Next-mat A tile is register-prefetched and consumed the following iter.
// ---------------------------------------------------------------------------
#define S_A_HI 0
#define S_A_LO 32768
#define S_B_HI 65536
#define S_B_LO 98304
#define S_BIAS 131072
#define SMEM_TOT (131072 + 512)

__global__ __launch_bounds__(256) void rgcn_gemm_mma(
    const float* __restrict__ x,
    const float* __restrict__ bias,
    float* __restrict__ out,
    int N)
{
    extern __shared__ unsigned char smem[];
    const int tid = threadIdx.x, wid = tid >> 5, lane = tid & 31;
    const int wm = wid & 3;          // 4 m-blocks of 32 rows
    const int wn = wid >> 2;         // 2 n-blocks of 64 cols
    const int m0 = blockIdx.x * 128;

    if (tid < 128) *(float*)(smem + S_BIAS + tid * 4) = bias[tid];

    float acc[2][8][4];
    #pragma unroll
    for (int i = 0; i < 2; i++)
        #pragma unroll
        for (int j = 0; j < 8; j++)
            #pragma unroll
            for (int t = 0; t < 4; t++) acc[i][j][t] = 0.f;

    // Precompute ldmatrix lane->row pieces.
    const int a_row = wm * 32 + (lane & 7) + ((lane >> 3) & 1) * 8;  // + mi*16
    const int a_cl  = lane >> 4;                                     // k-chunk sel
    const int b_row = wn * 64 + (lane & 7) + ((lane >> 4) << 3);     // + nj*16
    const int b_cl  = (lane >> 3) & 1;

    // A-load mapping: thread owns one contiguous half-row (16 float4 = 256B).
    const int arow = tid >> 1;           // 0..127
    const int ahalf = (tid & 1) * 16;    // float4 offset within row
    const int agr = m0 + arow;
    const bool avalid = (agr < N);

    float4 pref[16];
    float cnt_cur = 1.0f;

    // Preload mat 0 (g_H relation 0).
    {
        #pragma unroll
        for (int j = 0; j < 16; j++) pref[j] = make_float4(0.f, 0.f, 0.f, 0.f);
        if (avalid) {
            size_t base = (size_t)0 * N + agr;
            const float4* p = (const float4*)(g_H + base * IN_CH);
            #pragma unroll
            for (int j = 0; j < 16; j++) pref[j] = p[ahalf + j];
            cnt_cur = g_cnt[base];
        }
    }

    for (int mat = 0; mat < NMATS; mat++) {
        // ---- B copy first (L2-resident; latency overlaps A convert) ----
        const float4* wh = (const float4*)(g_Whi + (size_t)mat * 32768);
        const float4* wl = (const float4*)(g_Wlo + (size_t)mat * 32768);
        #pragma unroll
        for (int i = 0; i < 8; i++) {
            int idx = tid + i * 256;
            ((float4*)(smem + S_B_HI))[idx] = wh[idx];
            ((float4*)(smem + S_B_LO))[idx] = wl[idx];
        }
        // ---- convert prefetched A regs -> smem (mean-scale, hi/lo split) ----
        {
            float inv = (mat < 8) ? (1.0f / fmaxf(cnt_cur, 1.0f)) : 1.0f;
            #pragma unroll
            for (int j = 0; j < 16; j++) {
                float4 v = pref[j];
                v.x *= inv; v.y *= inv; v.z *= inv; v.w *= inv;
                __nv_bfloat162 h0 = __floats2bfloat162_rn(v.x, v.y);
                __nv_bfloat162 h1 = __floats2bfloat162_rn(v.z, v.w);
                __nv_bfloat162 l0 = __floats2bfloat162_rn(v.x - __bfloat162float(h0.x),
                                                          v.y - __bfloat162float(h0.y));
                __nv_bfloat162 l1 = __floats2bfloat162_rn(v.z - __bfloat162float(h1.x),
                                                          v.w - __bfloat162float(h1.y));
                int c4 = ahalf + j;
                uint32_t off = swz_off(arow, c4 >> 1) + (uint32_t)((c4 & 1) * 8);
                uint2 uh; uh.x = *(uint32_t*)&h0; uh.y = *(uint32_t*)&h1;
                uint2 ul; ul.x = *(uint32_t*)&l0; ul.y = *(uint32_t*)&l1;
                *(uint2*)(smem + S_A_HI + off) = uh;
                *(uint2*)(smem + S_A_LO + off) = ul;
            }
        }
        __syncthreads();

        // ---- prefetch next mat's A into regs (hidden under compute) ----
        if (mat + 1 < NMATS) {
            int matn = mat + 1;
            #pragma unroll
            for (int j = 0; j < 16; j++) pref[j] = make_float4(0.f, 0.f, 0.f, 0.f);
            if (avalid) {
                if (matn < 8) {
                    size_t base = (size_t)matn * N + agr;
                    const float4* p = (const float4*)(g_H + base * IN_CH);
                    #pragma unroll
                    for (int j = 0; j < 16; j++) pref[j] = p[ahalf + j];
                    cnt_cur = g_cnt[base];
                } else {
                    const float4* p = (const float4*)(x + (size_t)agr * IN_CH);
                    #pragma unroll
                    for (int j = 0; j < 16; j++) pref[j] = p[ahalf + j];
                }
            }
        }

        // ---- 3 passes x 8 k16-steps ----
        #pragma unroll
        for (int pass = 0; pass < 3; pass++) {
            uint32_t As = smem_u32(smem + ((pass == 1) ? S_A_LO : S_A_HI));
            uint32_t Bs = smem_u32(smem + ((pass == 2) ? S_B_LO : S_B_HI));
            #pragma unroll
            for (int ks = 0; ks < 8; ks++) {
                uint32_t a[2][4], b[4][4];
                #pragma unroll
                for (int mi = 0; mi < 2; mi++) {
                    int r = a_row + mi * 16;
                    ldsm4(a[mi], As + swz_off(r, ks * 2 + a_cl));
                }
                #pragma unroll
                for (int nj = 0; nj < 4; nj++) {
                    int r = b_row + nj * 16;
                    ldsm4(b[nj], Bs + swz_off(r, ks * 2 + b_cl));
                }
                #pragma unroll
                for (int mi = 0; mi < 2; mi++)
                    #pragma unroll
                    for (int n8 = 0; n8 < 8; n8++)
                        mma16816(acc[mi][n8], a[mi], b[n8 >> 1] + (n8 & 1) * 2);
            }
        }
        __syncthreads();
    }

    // ---- epilogue: d-frag rows (lane>>2, +8), cols (lane&3)*2 ----
    const float* sbias = (const float*)(smem + S_BIAS);
    #pragma unroll
    for (int mi = 0; mi < 2; mi++) {
        #pragma unroll
        for (int n8 = 0; n8 < 8; n8++) {
            int col = wn * 64 + n8 * 8 + (lane & 3) * 2;
            float b0 = sbias[col], b1 = sbias[col + 1];
            int r0 = m0 + wm * 32 + mi * 16 + (lane >> 2);
            if (r0 < N) {
                float2 o; o.x = acc[mi][n8][0] + b0; o.y = acc[mi][n8][1] + b1;
                *(float2*)(out + (size_t)r0 * OUT_CH + col) = o;
            }
            int r1 = r0 + 8;
            if (r1 < N) {
                float2 o; o.x = acc[mi][n8][2] + b0; o.y = acc[mi][n8][3] + b1;
                *(float2*)(out + (size_t)r1 * OUT_CH + col) = o;
            }
        }
    }
}

// ---------------------------------------------------------------------------
extern "C" void kernel_launch(void* const* d_in, const int* in_sizes, int n_in,
                              void* d_out, int out_size) {
    const float* x      = (const float*)d_in[0];
    const int* ei       = (const int*)d_in[1];   // int32 (JAX x64-off downcast)
    const int* et       = (const int*)d_in[2];   // int32
    const float* weight = (const float*)d_in[3];
    const float* root   = (const float*)d_in[4];
    const float* bias   = (const float*)d_in[5];
    float* out = (float*)d_out;

    int N = in_sizes[0] / IN_CH;
    int E = in_sizes[2];

    // Phase 0: pre-split/swizzle W.
    prep_w_kernel<<<dim3(NMATS, 8), 256>>>(weight, root);

    // Phase 1: zero the aggregation scratch.
    void* hp = nullptr; cudaGetSymbolAddress(&hp, g_H);
    void* cp = nullptr; cudaGetSymbolAddress(&cp, g_cnt);
    cudaMemsetAsync(hp, 0, (size_t)N_REL * N * IN_CH * sizeof(float), 0);
    cudaMemsetAsync(cp, 0, (size_t)N_REL * N * sizeof(float), 0);

    // Phase 2: edge scatter (warp per edge).
    {
        long long threads = (long long)E * 32;
        int blocks = (int)((threads + 255) / 256);
        rgcn_scatter_kernel<<<blocks, 256>>>(x, ei, et, E, N);
    }

    // Phase 3: mma.sync GEMM with register-prefetched A tiles.
    cudaFuncSetAttribute(rgcn_gemm_mma,
                         cudaFuncAttributeMaxDynamicSharedMemorySize, SMEM_TOT);
    rgcn_gemm_mma<<<(N + 127) / 128, 256, SMEM_TOT>>>(x, bias, out, N);
}

// round 11
// speedup vs baseline: 1.9528x; 1.1688x over previous
#include <cuda_runtime.h>
#include <cuda_bf16.h>
#include <cstdint>

#define N_NODES 100000
#define IN_CH 128
#define OUT_CH 128
#define N_REL 8
#define NMATS 9
#define N_EDGES_MAX 1600000
#define NSEG (N_REL * N_NODES)          // 800000 segments (r, dst)
#define SCAN_BLOCKS ((NSEG + 1023) / 1024)   // 782

// CSR over edges grouped by (relation, dst).
__device__ int g_cnt_i[NSEG];
__device__ int g_off[NSEG + 1];
__device__ int g_cur[NSEG];
__device__ int g_bsum[1024];
__device__ int g_edges[N_EDGES_MAX];
// Pre-split, pre-swizzled bf16 weight images (exact SMEM byte images).
__device__ __align__(16) unsigned char g_Whi[NMATS * 32768];
__device__ __align__(16) unsigned char g_Wlo[NMATS * 32768];

// ---------------------------------------------------------------------------
// ldmatrix-friendly swizzled layout for a [128 rows][128 bf16 cols] tile:
// 256B per row; 16B chunk index c (0..15) stored at (c ^ (row & 7)).
// ---------------------------------------------------------------------------
__device__ __forceinline__ uint32_t swz_off(int row, int chunk) {
    return (uint32_t)(row * 256 + ((chunk ^ (row & 7)) << 4));
}

// ---------------------------------------------------------------------------
// Phase 0: pre-split W (+root) into bf16 hi/lo, transposed (row=n, col=k).
// ---------------------------------------------------------------------------
__global__ void prep_w_kernel(const float* __restrict__ w,
                              const float* __restrict__ root) {
    int mat = blockIdx.x;
    int sub = blockIdx.y;
    const float* src = (mat < 8) ? (w + (size_t)mat * 16384) : root;
    unsigned char* dh = g_Whi + (size_t)mat * 32768;
    unsigned char* dl = g_Wlo + (size_t)mat * 32768;
    int end = (sub + 1) * 2048;
    for (int idx = sub * 2048 + threadIdx.x; idx < end; idx += blockDim.x) {
        int k = idx >> 7, n = idx & 127;
        float v = src[idx];
        __nv_bfloat16 hi = __float2bfloat16(v);
        __nv_bfloat16 lo = __float2bfloat16(v - __bfloat162float(hi));
        uint32_t off = swz_off(n, k >> 3) + (uint32_t)((k & 7) * 2);
        *(__nv_bfloat16*)(dh + off) = hi;
        *(__nv_bfloat16*)(dl + off) = lo;
    }
}

// ---------------------------------------------------------------------------
// CSR build: histogram, exclusive scan (3 kernels), bucket scatter.
// ---------------------------------------------------------------------------
__global__ void hist_kernel(const int* __restrict__ ei,
                            const int* __restrict__ et, int E, int N) {
    int e = blockIdx.x * blockDim.x + threadIdx.x;
    if (e >= E) return;
    int dst = ei[E + e];
    int r = et[e];
    if ((unsigned)dst >= (unsigned)N || (unsigned)r >= (unsigned)N_REL) return;
    atomicAdd(&g_cnt_i[r * N + dst], 1);
}

__global__ void scan1_kernel(int n) {
    __shared__ int sh[1024];
    int i = blockIdx.x * 1024 + threadIdx.x;
    int v = (i < n) ? g_cnt_i[i] : 0;
    sh[threadIdx.x] = v;
    __syncthreads();
    for (int d = 1; d < 1024; d <<= 1) {
        int t = (threadIdx.x >= d) ? sh[threadIdx.x - d] : 0;
        __syncthreads();
        sh[threadIdx.x] += t;
        __syncthreads();
    }
    if (i < n) g_off[i] = sh[threadIdx.x] - v;   // exclusive
    if (threadIdx.x == 1023) g_bsum[blockIdx.x] = sh[1023];
}

__global__ void scan2_kernel(int nb) {
    __shared__ int sh[1024];
    int v = (threadIdx.x < nb) ? g_bsum[threadIdx.x] : 0;
    sh[threadIdx.x] = v;
    __syncthreads();
    for (int d = 1; d < 1024; d <<= 1) {
        int t = (threadIdx.x >= d) ? sh[threadIdx.x - d] : 0;
        __syncthreads();
        sh[threadIdx.x] += t;
        __syncthreads();
    }
    if (threadIdx.x < nb) g_bsum[threadIdx.x] = sh[threadIdx.x] - v;  // exclusive
}

__global__ void scan3_kernel(int n, int E) {
    int i = blockIdx.x * 1024 + threadIdx.x;
    if (i < n) {
        int o = g_off[i] + g_bsum[blockIdx.x];
        g_off[i] = o;
        g_cur[i] = o;
    }
    if (i == 0) g_off[n] = E;
}

__global__ void bucket_kernel(const int* __restrict__ ei,
                              const int* __restrict__ et, int E, int N) {
    int e = blockIdx.x * blockDim.x + threadIdx.x;
    if (e >= E) return;
    int src = ei[e];
    int dst = ei[E + e];
    int r = et[e];
    if ((unsigned)src >= (unsigned)N || (unsigned)dst >= (unsigned)N ||
        (unsigned)r >= (unsigned)N_REL) return;
    int pos = atomicAdd(&g_cur[r * N + dst], 1);
    g_edges[pos] = src;
}

// ---------------------------------------------------------------------------
// mma.sync helpers (sm_80-class path)
// ---------------------------------------------------------------------------
__device__ __forceinline__ uint32_t smem_u32(const void* p) {
    uint32_t a;
    asm("{ .reg .u64 t; cvta.to.shared.u64 t, %1; cvt.u32.u64 %0, t; }"
        : "=r"(a) : "l"(p));
    return a;
}
__device__ __forceinline__ void ldsm4(uint32_t* r, uint32_t addr) {
    asm volatile("ldmatrix.sync.aligned.m8n8.x4.shared.b16 {%0,%1,%2,%3}, [%4];"
                 : "=r"(r[0]), "=r"(r[1]), "=r"(r[2]), "=r"(r[3]) : "r"(addr));
}
__device__ __forceinline__ void mma16816(float* d, const uint32_t* a,
                                         const uint32_t* b) {
    asm volatile(
        "mma.sync.aligned.m16n8k16.row.col.f32.bf16.bf16.f32 "
        "{%0,%1,%2,%3}, {%4,%5,%6,%7}, {%8,%9}, {%0,%1,%2,%3};"
        : "+f"(d[0]), "+f"(d[1]), "+f"(d[2]), "+f"(d[3])
        : "r"(a[0]), "r"(a[1]), "r"(a[2]), "r"(a[3]), "r"(b[0]), "r"(b[1]));
}

// ---------------------------------------------------------------------------
// Phase 3: fused GEMM. A tile per relation built by CSR gather of x rows
// (L2-resident) with fp32 mean, bf16 hi/lo split; mma.sync core unchanged.
// ---------------------------------------------------------------------------
#define S_A_HI 0
#define S_A_LO 32768
#define S_B_HI 65536
#define S_B_LO 98304
#define S_BIAS 131072
#define SMEM_TOT (131072 + 512)

__global__ __launch_bounds__(256) void rgcn_gemm_mma(
    const float* __restrict__ x,
    const float* __restrict__ bias,
    float* __restrict__ out,
    int N)
{
    extern __shared__ unsigned char smem[];
    const int tid = threadIdx.x, wid = tid >> 5, lane = tid & 31;
    const int wm = wid & 3;
    const int wn = wid >> 2;
    const int m0 = blockIdx.x * 128;

    if (tid < 128) *(float*)(smem + S_BIAS + tid * 4) = bias[tid];

    float acc[2][8][4];
    #pragma unroll
    for (int i = 0; i < 2; i++)
        #pragma unroll
        for (int j = 0; j < 8; j++)
            #pragma unroll
            for (int t = 0; t < 4; t++) acc[i][j][t] = 0.f;

    const int a_row = wm * 32 + (lane & 7) + ((lane >> 3) & 1) * 8;
    const int a_cl  = lane >> 4;
    const int b_row = wn * 64 + (lane & 7) + ((lane >> 4) << 3);
    const int b_cl  = (lane >> 3) & 1;

    for (int mat = 0; mat < NMATS; mat++) {
        // ---- B copy (L2-resident identity float4 copy) ----
        const float4* wh = (const float4*)(g_Whi + (size_t)mat * 32768);
        const float4* wl = (const float4*)(g_Wlo + (size_t)mat * 32768);
        #pragma unroll
        for (int i = 0; i < 8; i++) {
            int idx = tid + i * 256;
            ((float4*)(smem + S_B_HI))[idx] = wh[idx];
            ((float4*)(smem + S_B_LO))[idx] = wl[idx];
        }

        // ---- A tile: CSR gather (mat<8) or x row (mat==8), split hi/lo ----
        // Warp wid owns rows [wid*16, wid*16+16); lane covers col chunk lane*4.
        #pragma unroll 2
        for (int rr = 0; rr < 16; rr++) {
            int row = wid * 16 + rr;
            int gr = m0 + row;
            float4 a4 = make_float4(0.f, 0.f, 0.f, 0.f);
            if (gr < N) {
                if (mat < 8) {
                    int seg = mat * N + gr;
                    int lo = g_off[seg], hi = g_off[seg + 1];
                    for (int i = lo; i < hi; i++) {
                        int s = g_edges[i];
                        float4 v = ((const float4*)(x + (size_t)s * IN_CH))[lane];
                        a4.x += v.x; a4.y += v.y; a4.z += v.z; a4.w += v.w;
                    }
                    float inv = 1.0f / fmaxf((float)(hi - lo), 1.0f);
                    a4.x *= inv; a4.y *= inv; a4.z *= inv; a4.w *= inv;
                } else {
                    a4 = ((const float4*)(x + (size_t)gr * IN_CH))[lane];
                }
            }
            __nv_bfloat162 h0 = __floats2bfloat162_rn(a4.x, a4.y);
            __nv_bfloat162 h1 = __floats2bfloat162_rn(a4.z, a4.w);
            __nv_bfloat162 l0 = __floats2bfloat162_rn(a4.x - __bfloat162float(h0.x),
                                                      a4.y - __bfloat162float(h0.y));
            __nv_bfloat162 l1 = __floats2bfloat162_rn(a4.z - __bfloat162float(h1.x),
                                                      a4.w - __bfloat162float(h1.y));
            uint32_t off = swz_off(row, lane >> 1) + (uint32_t)((lane & 1) * 8);
            uint2 uh; uh.x = *(uint32_t*)&h0; uh.y = *(uint32_t*)&h1;
            uint2 ul; ul.x = *(uint32_t*)&l0; ul.y = *(uint32_t*)&l1;
            *(uint2*)(smem + S_A_HI + off) = uh;
            *(uint2*)(smem + S_A_LO + off) = ul;
        }
        __syncthreads();

        // ---- 3 passes x 8 k16-steps ----
        #pragma unroll
        for (int pass = 0; pass < 3; pass++) {
            uint32_t As = smem_u32(smem + ((pass == 1) ? S_A_LO : S_A_HI));
            uint32_t Bs = smem_u32(smem + ((pass == 2) ? S_B_LO : S_B_HI));
            #pragma unroll
            for (int ks = 0; ks < 8; ks++) {
                uint32_t a[2][4], b[4][4];
                #pragma unroll
                for (int mi = 0; mi < 2; mi++) {
                    int r = a_row + mi * 16;
                    ldsm4(a[mi], As + swz_off(r, ks * 2 + a_cl));
                }
                #pragma unroll
                for (int nj = 0; nj < 4; nj++) {
                    int r = b_row + nj * 16;
                    ldsm4(b[nj], Bs + swz_off(r, ks * 2 + b_cl));
                }
                #pragma unroll
                for (int mi = 0; mi < 2; mi++)
                    #pragma unroll
                    for (int n8 = 0; n8 < 8; n8++)
                        mma16816(acc[mi][n8], a[mi], b[n8 >> 1] + (n8 & 1) * 2);
            }
        }
        __syncthreads();
    }

    // ---- epilogue ----
    const float* sbias = (const float*)(smem + S_BIAS);
    #pragma unroll
    for (int mi = 0; mi < 2; mi++) {
        #pragma unroll
        for (int n8 = 0; n8 < 8; n8++) {
            int col = wn * 64 + n8 * 8 + (lane & 3) * 2;
            float b0 = sbias[col], b1 = sbias[col + 1];
            int r0 = m0 + wm * 32 + mi * 16 + (lane >> 2);
            if (r0 < N) {
                float2 o; o.x = acc[mi][n8][0] + b0; o.y = acc[mi][n8][1] + b1;
                *(float2*)(out + (size_t)r0 * OUT_CH + col) = o;
            }
            int r1 = r0 + 8;
            if (r1 < N) {
                float2 o; o.x = acc[mi][n8][2] + b0; o.y = acc[mi][n8][3] + b1;
                *(float2*)(out + (size_t)r1 * OUT_CH + col) = o;
            }
        }
    }
}

// ---------------------------------------------------------------------------
extern "C" void kernel_launch(void* const* d_in, const int* in_sizes, int n_in,
                              void* d_out, int out_size) {
    const float* x      = (const float*)d_in[0];
    const int* ei       = (const int*)d_in[1];   // int32 (JAX x64-off downcast)
    const int* et       = (const int*)d_in[2];   // int32
    const float* weight = (const float*)d_in[3];
    const float* root   = (const float*)d_in[4];
    const float* bias   = (const float*)d_in[5];
    float* out = (float*)d_out;

    int N = in_sizes[0] / IN_CH;
    int E = in_sizes[2];
    int nseg = N_REL * N;
    int scan_blocks = (nseg + 1023) / 1024;

    // Phase 0: pre-split/swizzle W.
    prep_w_kernel<<<dim3(NMATS, 8), 256>>>(weight, root);

    // Phase 1: CSR build.
    void* cp = nullptr; cudaGetSymbolAddress(&cp, g_cnt_i);
    cudaMemsetAsync(cp, 0, (size_t)nseg * sizeof(int), 0);
    hist_kernel<<<(E + 255) / 256, 256>>>(ei, et, E, N);
    scan1_kernel<<<scan_blocks, 1024>>>(nseg);
    scan2_kernel<<<1, 1024>>>(scan_blocks);
    scan3_kernel<<<scan_blocks, 1024>>>(nseg, E);
    bucket_kernel<<<(E + 255) / 256, 256>>>(ei, et, E, N);

    // Phase 2: gather-GEMM.
    cudaFuncSetAttribute(rgcn_gemm_mma,
                         cudaFuncAttributeMaxDynamicSharedMemorySize, SMEM_TOT);
    rgcn_gemm_mma<<<(N + 127) / 128, 256, SMEM_TOT>>>(x, bias, out, N);
}